// round 7
// baseline (speedup 1.0000x reference)
#include <cuda_runtime.h>
#include <cuda_fp16.h>
#include <stdint.h>
#include <float.h>

#define NROWS   65536
#define DIMS    256
#define NCODES  1024
#define TM      128        // rows per block
#define TC      64         // codes per chunk
#define NCHUNK  (NCODES / TC)
#define MARGIN  6e-3f      // ~12 sigma of fp16-accumulation distance error
#define MAXC    10         // per-thread candidate cap
#define RSB     272        // smem row stride bytes (136 half2) -> conflict-free LDS.128

// ---- smem layout (bytes) -------------------------------------------------
#define OFF_Z      0                        // 128 x RSB                  34816
#define OFF_E0     34816                    // 64 x RSB                   17408
#define OFF_E1     52224                    //                            17408
#define OFF_LIST   69632                    // u64[256][MAXC]             20480
#define OFF_E2     90112                    // f32[1024]                   4096
#define OFF_Z2     94208                    // f32[128]                     512
#define OFF_RMS    94720                    // f32[256][8]                 8192
#define OFF_FMIN   102912                   // i32[128]                     512
#define OFF_BEST   103424                   // u64[128]                    1024
#define OFF_IDX    104448                   // i32[128]                     512
#define OFF_ROVF   104960                   // i32[128]                     512
#define OFF_OVFL   105472                   // i32 count + i32[128]         520
#define OFF_RED    105992                   // double[256]                 2048
#define SMEM_BYTES (OFF_RED + 2048)

__device__ float  g_e2[NCODES];
__device__ double g_loss_accum;

// ---------------------------------------------------------------------------
__global__ void vq_prep(const float* __restrict__ emb) {
    if (blockIdx.x == 0 && threadIdx.x == 0) g_loss_accum = 0.0;
    int warp = (blockIdx.x * blockDim.x + threadIdx.x) >> 5;
    int lane = threadIdx.x & 31;
    if (warp < NCODES) {
        const float* row = emb + warp * DIMS;
        float s = 0.f;
#pragma unroll
        for (int i = 0; i < DIMS / 32; i++) {
            float v = row[lane + 32 * i];
            s = __fadd_rn(s, __fmul_rn(v, v));
        }
#pragma unroll
        for (int o = 16; o > 0; o >>= 1)
            s = __fadd_rn(s, __shfl_down_sync(0xffffffffu, s, o));
        if (lane == 0) g_e2[warp] = s;
    }
}

// ---------------------------------------------------------------------------
// stage one 64x256 e-chunk (fp32 -> half2 packed along k)
__device__ __forceinline__ void stage_E(const float* __restrict__ eblk,
                                        char* et, int tid) {
#pragma unroll 4
    for (int i = tid; i < TC * (DIMS / 4); i += 256) {
        int c  = i >> 6;
        int k4 = i & 63;
        float4 v = __ldg(&((const float4*)eblk)[(size_t)c * (DIMS / 4) + k4]);
        __half2 h0 = __floats2half2_rn(v.x, v.y);
        __half2 h1 = __floats2half2_rn(v.z, v.w);
        *(uint2*)(et + (size_t)c * RSB + k4 * 8) =
            make_uint2(*(uint32_t*)&h0, *(uint32_t*)&h1);
    }
}

// exact fp32 distance, reference formula/rounding; packed for lowest-idx tiebreak
__device__ __forceinline__ unsigned long long exact_dist(
    const float* __restrict__ zrow, const float* __restrict__ emb,
    int code, float z2, const float* __restrict__ e2all) {
    const float4* zr = (const float4*)zrow;
    const float4* er = (const float4*)(emb + (size_t)code * DIMS);
    float d0 = 0.f, d1 = 0.f, d2 = 0.f, d3 = 0.f;
#pragma unroll 8
    for (int k4 = 0; k4 < DIMS / 4; k4++) {
        float4 zv = __ldg(&zr[k4]);
        float4 ev = __ldg(&er[k4]);
        d0 = fmaf(zv.x, ev.x, d0);
        d1 = fmaf(zv.y, ev.y, d1);
        d2 = fmaf(zv.z, ev.z, d2);
        d3 = fmaf(zv.w, ev.w, d3);
    }
    float dot  = __fadd_rn(__fadd_rn(d0, d1), __fadd_rn(d2, d3));
    float t    = __fadd_rn(z2, e2all[code]);
    float dist = __fsub_rn(t, __fmul_rn(2.0f, dot));
    return ((unsigned long long)__float_as_uint(dist) << 32) | (unsigned)code;
}

// ---------------------------------------------------------------------------
__global__ void __launch_bounds__(256, 2)
vq_main(const float* __restrict__ z, const float* __restrict__ emb,
        float* __restrict__ out) {
    extern __shared__ char sm[];
    float*  e2all = (float*)(sm + OFF_E2);
    float*  z2sm  = (float*)(sm + OFF_Z2);
    float*  rmS   = (float*)(sm + OFF_RMS);
    int*    fminI = (int*)(sm + OFF_FMIN);
    unsigned long long* bestU = (unsigned long long*)(sm + OFF_BEST);
    int*    idxs  = (int*)(sm + OFF_IDX);
    int*    rowOvf= (int*)(sm + OFF_ROVF);
    int*    ovfl  = (int*)(sm + OFF_OVFL);
    double* red   = (double*)(sm + OFF_RED);
    unsigned long long* lst =
        (unsigned long long*)(sm + OFF_LIST) + (size_t)threadIdx.x * MAXC;

    const int tid  = threadIdx.x;
    const int lane = tid & 31;
    const int warp = tid >> 5;
    const int wr   = warp >> 2;          // 0-1: 64-row group
    const int wc   = warp & 3;           // 0-3: 16-code group
    const int tr   = lane >> 2;          // 0-7
    const int tc   = lane & 3;           // 0-3
    const int rowBase = blockIdx.x * TM;
    const float* zblk = z + (size_t)rowBase * DIMS;

    if (tid < TM) {
        fminI[tid]  = 0x7f800000;
        bestU[tid]  = ~0ull;
        rowOvf[tid] = 0;
    }
    if (tid == 0) ovfl[0] = 0;

    // ---- stage z tile (fp32 -> half2) ----
#pragma unroll 4
    for (int i = tid; i < TM * (DIMS / 4); i += 256) {
        int r  = i >> 6;
        int k4 = i & 63;
        float4 v = __ldg(&((const float4*)zblk)[(size_t)r * (DIMS / 4) + k4]);
        __half2 h0 = __floats2half2_rn(v.x, v.y);
        __half2 h1 = __floats2half2_rn(v.z, v.w);
        *(uint2*)(sm + OFF_Z + (size_t)r * RSB + k4 * 8) =
            make_uint2(*(uint32_t*)&h0, *(uint32_t*)&h1);
    }
    for (int i = tid; i < NCODES; i += 256) e2all[i] = g_e2[i];
    if (tid < TM) {
        const float4* zr = (const float4*)(zblk + (size_t)tid * DIMS);
        float s = 0.f;
        for (int k4 = 0; k4 < DIMS / 4; k4++) {
            float4 v = __ldg(&zr[k4]);
            s = __fadd_rn(s, __fmul_rn(v.x, v.x));
            s = __fadd_rn(s, __fmul_rn(v.y, v.y));
            s = __fadd_rn(s, __fmul_rn(v.z, v.z));
            s = __fadd_rn(s, __fmul_rn(v.w, v.w));
        }
        z2sm[tid] = s;
    }
    stage_E(emb, sm + OFF_E0, tid);
    __syncthreads();

    // per-thread fragment base pointers
    const char* zb = sm + OFF_Z + (size_t)(wr * 64 + tr) * RSB;   // rows tr+8i
    const int   cb = wc * 16 + tc;                                 // codes cb+4j
    float z2sl[8];
#pragma unroll
    for (int i = 0; i < 8; i++) z2sl[i] = z2sm[wr * 64 + tr + 8 * i];

    float rm[8];
#pragma unroll
    for (int i = 0; i < 8; i++) rm[i] = FLT_MAX;
    int cn = 0;
    bool ovfflag = false;

    auto insert_cand = [&](float da, int tag) {
        if (cn == MAXC) {
            float* rs = rmS + tid * 8;
#pragma unroll
            for (int i = 0; i < 8; i++) rs[i] = rm[i];
            int w = 0;
            for (int t = 0; t < MAXC; t++) {
                unsigned long long e = lst[t];
                float v = __uint_as_float((unsigned)(e >> 32));
                int s = ((int)(e & 0x1FFFu)) >> 10;
                if (v <= rs[s] + MARGIN) lst[w++] = e;
            }
            cn = w;
        }
        if (cn < MAXC)
            lst[cn++] = ((unsigned long long)__float_as_uint(da) << 32) | (unsigned)tag;
        else
            ovfflag = true;   // resolved to rows after the loop
    };
#define TRACK(da, slot, rmv, code)                                   \
    { float _d = (da);                                               \
      if (_d < rmv) rmv = _d;                                        \
      if (_d <= rmv + MARGIN) insert_cand(_d, ((slot) << 10) | (code)); }

    // ================= chunk loop: HFMA2 GEMM + candidate tracking =========
    for (int c = 0; c < NCHUNK; c++) {
        const int bb = c & 1;
        const char* eb = sm + (bb ? OFF_E1 : OFF_E0) + (size_t)cb * RSB;
        if (c + 1 < NCHUNK)
            stage_E(emb + (size_t)(c + 1) * TC * DIMS,
                    sm + (bb ? OFF_E0 : OFF_E1), tid);

        __half2 acc[8][4];
#pragma unroll
        for (int i = 0; i < 8; i++)
#pragma unroll
            for (int j = 0; j < 4; j++) acc[i][j] = __floats2half2_rn(0.f, 0.f);

#pragma unroll 2
        for (int kg = 0; kg < 32; kg++) {       // 4 k-pairs (= 8 dims) per iter
            uint4 zf[8], ef[4];
#pragma unroll
            for (int i = 0; i < 8; i++)
                zf[i] = *(const uint4*)(zb + (size_t)i * 8 * RSB + kg * 16);
#pragma unroll
            for (int j = 0; j < 4; j++)
                ef[j] = *(const uint4*)(eb + (size_t)j * 4 * RSB + kg * 16);
#pragma unroll
            for (int i = 0; i < 8; i++) {
                const __half2* zh = (const __half2*)&zf[i];
#pragma unroll
                for (int j = 0; j < 4; j++) {
                    const __half2* eh = (const __half2*)&ef[j];
                    acc[i][j] = __hfma2(zh[0], eh[0], acc[i][j]);
                    acc[i][j] = __hfma2(zh[1], eh[1], acc[i][j]);
                    acc[i][j] = __hfma2(zh[2], eh[2], acc[i][j]);
                    acc[i][j] = __hfma2(zh[3], eh[3], acc[i][j]);
                }
            }
        }

        // distances -> per-slot running min + candidate list
        const int chunkBase = c * TC;
#pragma unroll
        for (int i = 0; i < 8; i++) {
            float z2e = z2sl[i];
#pragma unroll
            for (int j = 0; j < 4; j++) {
                int lc   = cb + 4 * j;
                int code = chunkBase + lc;
                float2 f = __half22float2(acc[i][j]);
                float dot = f.x + f.y;
                float da  = fmaf(-2.0f, dot, z2e + e2all[code]);
                TRACK(da, i, rm[i], code);
            }
        }
        __syncthreads();
    }

    // ---- merge per-row approx minima ----
#pragma unroll
    for (int i = 0; i < 8; i++)
        atomicMin(&fminI[wr * 64 + tr + 8 * i], __float_as_int(rm[i]));
    if (ovfflag)           // list overflowed: conservatively flag all 8 rows
#pragma unroll
        for (int i = 0; i < 8; i++) rowOvf[wr * 64 + tr + 8 * i] = 1;
    __syncthreads();

    // ---- exact rescore of surviving candidates ----
    for (int t = 0; t < cn; t++) {
        unsigned long long e = lst[t];
        float v  = __uint_as_float((unsigned)(e >> 32));
        int tag  = (int)(e & 0x1FFFu);
        int s    = tag >> 10;
        int code = tag & 1023;
        int row  = wr * 64 + tr + 8 * s;
        if (v <= __int_as_float(fminI[row]) + MARGIN) {
            unsigned long long p =
                exact_dist(zblk + (size_t)row * DIMS, emb, code, z2sm[row], e2all);
            atomicMin(&bestU[row], p);
        }
    }
    __syncthreads();

    // ---- overflow rows: full exact scan (correct, ~never taken) ----
    if (tid < TM && rowOvf[tid]) {
        int p = atomicAdd(&ovfl[0], 1);
        ovfl[1 + p] = tid;
    }
    __syncthreads();
    int novf = ovfl[0];
    for (int f = 0; f < novf; f++) {
        int row = ovfl[1 + f];
        float z2r = z2sm[row];
        for (int code = tid; code < NCODES; code += 256) {
            unsigned long long p =
                exact_dist(zblk + (size_t)row * DIMS, emb, code, z2r, e2all);
            atomicMin(&bestU[row], p);
        }
    }
    if (novf) __syncthreads();

    if (tid < TM) idxs[tid] = (int)(bestU[tid] & 0xffffffffull);
    __syncthreads();

    // ================= epilogue: gather / STE / loss ======================
    double lsum = 0.0;
    float* outblk = out + (size_t)rowBase * DIMS;
    for (int i = tid; i < TM * (DIMS / 4); i += 256) {
        int r  = i >> 6;
        int k4 = i & 63;
        float4 zv = __ldg(&((const float4*)zblk)[(size_t)r * (DIMS / 4) + k4]);
        float4 qv = __ldg(&((const float4*)(emb + (size_t)idxs[r] * DIMS))[k4]);
        float4 ov; float d;
        d = __fsub_rn(qv.x, zv.x); ov.x = __fadd_rn(zv.x, d); lsum += (double)__fmul_rn(d, d);
        d = __fsub_rn(qv.y, zv.y); ov.y = __fadd_rn(zv.y, d); lsum += (double)__fmul_rn(d, d);
        d = __fsub_rn(qv.z, zv.z); ov.z = __fadd_rn(zv.z, d); lsum += (double)__fmul_rn(d, d);
        d = __fsub_rn(qv.w, zv.w); ov.w = __fadd_rn(zv.w, d); lsum += (double)__fmul_rn(d, d);
        ((float4*)outblk)[i] = ov;
    }
    red[tid] = lsum;
    __syncthreads();
    for (int s = 128; s > 0; s >>= 1) {
        if (tid < s) red[tid] += red[tid + s];
        __syncthreads();
    }
    if (tid == 0) atomicAdd(&g_loss_accum, red[0]);
}

// ---------------------------------------------------------------------------
__global__ void vq_finalize(float* __restrict__ out, int out_size) {
    double mean = g_loss_accum / (double)((size_t)NROWS * DIMS);
    float loss = (float)(0.5 * mean);
    out[out_size - 2] = loss;   // commitment_loss
    out[out_size - 1] = loss;   // emb_loss
}

// ---------------------------------------------------------------------------
extern "C" void kernel_launch(void* const* d_in, const int* in_sizes, int n_in,
                              void* d_out, int out_size) {
    const float* z   = (const float*)d_in[0];
    const float* emb = (const float*)d_in[1];
    if (n_in >= 2 && in_sizes[0] == NCODES * DIMS && in_sizes[1] == NROWS * DIMS) {
        emb = (const float*)d_in[0];
        z   = (const float*)d_in[1];
    }
    float* out = (float*)d_out;

    vq_prep<<<(NCODES * 32 + 255) / 256, 256>>>(emb);

    cudaFuncSetAttribute(vq_main, cudaFuncAttributeMaxDynamicSharedMemorySize,
                         SMEM_BYTES);
    vq_main<<<NROWS / TM, 256, SMEM_BYTES>>>(z, emb, out);

    vq_finalize<<<1, 1>>>(out, out_size);
}

// round 8
// speedup vs baseline: 14.0261x; 14.0261x over previous
#include <cuda_runtime.h>
#include <stdint.h>
#include <float.h>

#define NROWS   65536
#define DIMS    256
#define NCODES  1024
#define TM      64         // rows per block
#define TC      64         // codes per chunk
#define NCHUNK  (NCODES / TC)
#define MARGIN  1e-4f      // ~25x fp32 summation-order bound (4e-6)
#define MAXC    8          // per-thread candidate cap
#define RSB     1040       // f32 row stride bytes (260 words) -> conflict-free frags

// ---- smem layout (bytes) -------------------------------------------------
#define OFF_Z      0                        // 64 x RSB                   66560
#define OFF_E0     66560                    // 64 x RSB                   66560
#define OFF_E1     133120                   //                            66560
#define OFF_LIST   199680                   // u64[256][MAXC]             16384
#define OFF_E2     216064                   // f32[1024]                   4096
#define OFF_Z2     220160                   // f32[64]                      256
#define OFF_RMS    220416                   // f32[256][4]                 4096
#define OFF_FMIN   224512                   // i32[64]                      256
#define OFF_BEST   224768                   // u64[64]                      512
#define OFF_IDX    225280                   // i32[64]                      256
#define OFF_ROVF   225536                   // i32[64]                      256
#define OFF_OVFL   225792                   // i32 count + i32[64]          264
#define OFF_RED    226056                   // double[256]                 2048
#define SMEM_BYTES (OFF_RED + 2048)

__device__ float  g_e2[NCODES];
__device__ double g_loss_accum;

// packed f32x2 FMA: acc.lo += a.lo*b.lo, acc.hi += a.hi*b.hi
__device__ __forceinline__ void fma2(unsigned long long& acc,
                                     unsigned long long a,
                                     unsigned long long b) {
    asm("fma.rn.f32x2 %0, %1, %2, %0;" : "+l"(acc) : "l"(a), "l"(b));
}
__device__ __forceinline__ float2 unpack2(unsigned long long v) {
    float lo, hi;
    asm("mov.b64 {%0,%1}, %2;" : "=f"(lo), "=f"(hi) : "l"(v));
    return make_float2(lo, hi);
}

// ---------------------------------------------------------------------------
__global__ void vq_prep(const float* __restrict__ emb) {
    if (blockIdx.x == 0 && threadIdx.x == 0) g_loss_accum = 0.0;
    int warp = (blockIdx.x * blockDim.x + threadIdx.x) >> 5;
    int lane = threadIdx.x & 31;
    if (warp < NCODES) {
        const float* row = emb + warp * DIMS;
        float s = 0.f;
#pragma unroll
        for (int i = 0; i < DIMS / 32; i++) {
            float v = row[lane + 32 * i];
            s = __fadd_rn(s, __fmul_rn(v, v));
        }
#pragma unroll
        for (int o = 16; o > 0; o >>= 1)
            s = __fadd_rn(s, __shfl_down_sync(0xffffffffu, s, o));
        if (lane == 0) g_e2[warp] = s;
    }
}

// stage one 64x256 e-chunk: plain fp32 copy (no conversion)
__device__ __forceinline__ void stage_E(const float* __restrict__ eblk,
                                        char* et, int tid) {
#pragma unroll 4
    for (int i = tid; i < TC * (DIMS / 4); i += 256) {
        int c  = i >> 6;
        int k4 = i & 63;
        float4 v = __ldg(&((const float4*)eblk)[(size_t)c * (DIMS / 4) + k4]);
        *(float4*)(et + (size_t)c * RSB + k4 * 16) = v;
    }
}

// canonical exact fp32 distance (R1-proven formula/rounding) + tiebreak pack
__device__ __forceinline__ unsigned long long exact_dist(
    const float* __restrict__ zrow, const float* __restrict__ emb,
    int code, float z2, const float* __restrict__ e2all) {
    const float4* zr = (const float4*)zrow;
    const float4* er = (const float4*)(emb + (size_t)code * DIMS);
    float d0 = 0.f, d1 = 0.f, d2 = 0.f, d3 = 0.f;
#pragma unroll 8
    for (int k4 = 0; k4 < DIMS / 4; k4++) {
        float4 zv = __ldg(&zr[k4]);
        float4 ev = __ldg(&er[k4]);
        d0 = fmaf(zv.x, ev.x, d0);
        d1 = fmaf(zv.y, ev.y, d1);
        d2 = fmaf(zv.z, ev.z, d2);
        d3 = fmaf(zv.w, ev.w, d3);
    }
    float dot  = __fadd_rn(__fadd_rn(d0, d1), __fadd_rn(d2, d3));
    float t    = __fadd_rn(z2, e2all[code]);
    float dist = __fsub_rn(t, __fmul_rn(2.0f, dot));
    return ((unsigned long long)__float_as_uint(dist) << 32) | (unsigned)code;
}

// ---------------------------------------------------------------------------
__global__ void __launch_bounds__(256, 1)
vq_main(const float* __restrict__ z, const float* __restrict__ emb,
        float* __restrict__ out) {
    extern __shared__ char sm[];
    float*  e2all = (float*)(sm + OFF_E2);
    float*  z2sm  = (float*)(sm + OFF_Z2);
    float*  rmS   = (float*)(sm + OFF_RMS);
    int*    fminI = (int*)(sm + OFF_FMIN);
    unsigned long long* bestU = (unsigned long long*)(sm + OFF_BEST);
    int*    idxs  = (int*)(sm + OFF_IDX);
    int*    rowOvf= (int*)(sm + OFF_ROVF);
    int*    ovfl  = (int*)(sm + OFF_OVFL);
    double* red   = (double*)(sm + OFF_RED);
    unsigned long long* lst =
        (unsigned long long*)(sm + OFF_LIST) + (size_t)threadIdx.x * MAXC;

    const int tid  = threadIdx.x;
    const int lane = tid & 31;
    const int warp = tid >> 5;
    const int wr   = warp >> 2;          // 0-1: 32-row group
    const int wc   = warp & 3;           // 0-3: 16-code group
    const int tr   = lane >> 2;          // 0-7
    const int tc   = lane & 3;           // 0-3
    const int rowBase = blockIdx.x * TM;
    const float* zblk = z + (size_t)rowBase * DIMS;

    if (tid < TM) {
        fminI[tid]  = 0x7f800000;
        bestU[tid]  = ~0ull;
        rowOvf[tid] = 0;
    }
    if (tid == 0) ovfl[0] = 0;

    // ---- stage z tile (plain fp32) ----
#pragma unroll 4
    for (int i = tid; i < TM * (DIMS / 4); i += 256) {
        int r  = i >> 6;
        int k4 = i & 63;
        float4 v = __ldg(&((const float4*)zblk)[(size_t)r * (DIMS / 4) + k4]);
        *(float4*)(sm + OFF_Z + (size_t)r * RSB + k4 * 16) = v;
    }
    for (int i = tid; i < NCODES; i += 256) e2all[i] = g_e2[i];
    if (tid < TM) {
        const float4* zr = (const float4*)(zblk + (size_t)tid * DIMS);
        float s = 0.f;
        for (int k4 = 0; k4 < DIMS / 4; k4++) {
            float4 v = __ldg(&zr[k4]);
            s = __fadd_rn(s, __fmul_rn(v.x, v.x));
            s = __fadd_rn(s, __fmul_rn(v.y, v.y));
            s = __fadd_rn(s, __fmul_rn(v.z, v.z));
            s = __fadd_rn(s, __fmul_rn(v.w, v.w));
        }
        z2sm[tid] = s;
    }
    stage_E(emb, sm + OFF_E0, tid);
    __syncthreads();

    const char* zb = sm + OFF_Z + (size_t)(wr * 32 + tr) * RSB;  // rows +8i
    const int   cb = wc * 16 + tc;                                // codes +4j
    float z2sl[4];
#pragma unroll
    for (int i = 0; i < 4; i++) z2sl[i] = z2sm[wr * 32 + tr + 8 * i];

    float rm[4];
#pragma unroll
    for (int i = 0; i < 4; i++) rm[i] = FLT_MAX;
    int cn = 0;
    bool ovfflag = false;

    auto insert_cand = [&](float da, int tag) {
        if (cn == MAXC) {
            float* rs = rmS + tid * 4;
#pragma unroll
            for (int i = 0; i < 4; i++) rs[i] = rm[i];
            int w = 0;
            for (int t = 0; t < MAXC; t++) {
                unsigned long long e = lst[t];
                float v = __uint_as_float((unsigned)(e >> 32));
                int s = ((int)(e & 0xFFFu)) >> 10;
                if (v <= rs[s] + MARGIN) lst[w++] = e;
            }
            cn = w;
        }
        if (cn < MAXC)
            lst[cn++] = ((unsigned long long)__float_as_uint(da) << 32) | (unsigned)tag;
        else
            ovfflag = true;
    };
#define TRACK(da, slot, rmv, code)                                   \
    { float _d = (da);                                               \
      if (_d < rmv) rmv = _d;                                        \
      if (_d <= rmv + MARGIN) insert_cand(_d, ((slot) << 10) | (code)); }

    // ================= chunk loop: FFMA2 GEMM + candidate tracking =========
    for (int c = 0; c < NCHUNK; c++) {
        const int bb = c & 1;
        const char* eb = sm + (bb ? OFF_E1 : OFF_E0) + (size_t)cb * RSB;
        if (c + 1 < NCHUNK)
            stage_E(emb + (size_t)(c + 1) * TC * DIMS,
                    sm + (bb ? OFF_E0 : OFF_E1), tid);

        unsigned long long acc[4][4];
#pragma unroll
        for (int i = 0; i < 4; i++)
#pragma unroll
            for (int j = 0; j < 4; j++) acc[i][j] = 0ull;

#pragma unroll 4
        for (int kg = 0; kg < DIMS / 4; kg++) {   // 16 B = 2 f32x2 = 4 dims
            ulonglong2 zf[4], ef[4];
#pragma unroll
            for (int i = 0; i < 4; i++)
                zf[i] = *(const ulonglong2*)(zb + (size_t)i * 8 * RSB + kg * 16);
#pragma unroll
            for (int j = 0; j < 4; j++)
                ef[j] = *(const ulonglong2*)(eb + (size_t)j * 4 * RSB + kg * 16);
#pragma unroll
            for (int i = 0; i < 4; i++)
#pragma unroll
                for (int j = 0; j < 4; j++) {
                    fma2(acc[i][j], zf[i].x, ef[j].x);
                    fma2(acc[i][j], zf[i].y, ef[j].y);
                }
        }

        const int chunkBase = c * TC;
#pragma unroll
        for (int i = 0; i < 4; i++) {
            float z2e = z2sl[i];
#pragma unroll
            for (int j = 0; j < 4; j++) {
                int code = chunkBase + cb + 4 * j;
                float2 f = unpack2(acc[i][j]);
                float da = fmaf(-2.0f, f.x + f.y, z2e + e2all[code]);
                TRACK(da, i, rm[i], code);
            }
        }
        __syncthreads();
    }

    // ---- merge per-row approx minima ----
#pragma unroll
    for (int i = 0; i < 4; i++)
        atomicMin(&fminI[wr * 32 + tr + 8 * i], __float_as_int(rm[i]));
    if (ovfflag)
#pragma unroll
        for (int i = 0; i < 4; i++) rowOvf[wr * 32 + tr + 8 * i] = 1;
    __syncthreads();

    // ---- exact rescore of surviving candidates (canonical formula) ----
    for (int t = 0; t < cn; t++) {
        unsigned long long e = lst[t];
        float v  = __uint_as_float((unsigned)(e >> 32));
        int tag  = (int)(e & 0xFFFu);
        int s    = tag >> 10;
        int code = tag & 1023;
        int row  = wr * 32 + tr + 8 * s;
        if (v <= __int_as_float(fminI[row]) + MARGIN) {
            unsigned long long p =
                exact_dist(zblk + (size_t)row * DIMS, emb, code, z2sm[row], e2all);
            atomicMin(&bestU[row], p);
        }
    }
    __syncthreads();

    // ---- overflow rows: full exact scan (safety net, ~never taken) ----
    if (tid < TM && rowOvf[tid]) {
        int p = atomicAdd(&ovfl[0], 1);
        ovfl[1 + p] = tid;
    }
    __syncthreads();
    int novf = ovfl[0];
    for (int f = 0; f < novf; f++) {
        int row = ovfl[1 + f];
        float z2r = z2sm[row];
        for (int code = tid; code < NCODES; code += 256) {
            unsigned long long p =
                exact_dist(zblk + (size_t)row * DIMS, emb, code, z2r, e2all);
            atomicMin(&bestU[row], p);
        }
    }
    if (novf) __syncthreads();

    if (tid < TM) idxs[tid] = (int)(bestU[tid] & 0xffffffffull);
    __syncthreads();

    // ================= epilogue: gather / STE / loss ======================
    double lsum = 0.0;
    float* outblk = out + (size_t)rowBase * DIMS;
#pragma unroll 4
    for (int i = tid; i < TM * (DIMS / 4); i += 256) {
        int r  = i >> 6;
        int k4 = i & 63;
        float4 zv = *(const float4*)(sm + OFF_Z + (size_t)r * RSB + k4 * 16);
        float4 qv = __ldg(&((const float4*)(emb + (size_t)idxs[r] * DIMS))[k4]);
        float4 ov; float d;
        d = __fsub_rn(qv.x, zv.x); ov.x = __fadd_rn(zv.x, d); lsum += (double)__fmul_rn(d, d);
        d = __fsub_rn(qv.y, zv.y); ov.y = __fadd_rn(zv.y, d); lsum += (double)__fmul_rn(d, d);
        d = __fsub_rn(qv.z, zv.z); ov.z = __fadd_rn(zv.z, d); lsum += (double)__fmul_rn(d, d);
        d = __fsub_rn(qv.w, zv.w); ov.w = __fadd_rn(zv.w, d); lsum += (double)__fmul_rn(d, d);
        ((float4*)outblk)[i] = ov;
    }
    red[tid] = lsum;
    __syncthreads();
    for (int s = 128; s > 0; s >>= 1) {
        if (tid < s) red[tid] += red[tid + s];
        __syncthreads();
    }
    if (tid == 0) atomicAdd(&g_loss_accum, red[0]);
}

// ---------------------------------------------------------------------------
__global__ void vq_finalize(float* __restrict__ out, int out_size) {
    double mean = g_loss_accum / (double)((size_t)NROWS * DIMS);
    float loss = (float)(0.5 * mean);
    out[out_size - 2] = loss;   // commitment_loss
    out[out_size - 1] = loss;   // emb_loss
}

// ---------------------------------------------------------------------------
extern "C" void kernel_launch(void* const* d_in, const int* in_sizes, int n_in,
                              void* d_out, int out_size) {
    const float* z   = (const float*)d_in[0];
    const float* emb = (const float*)d_in[1];
    if (n_in >= 2 && in_sizes[0] == NCODES * DIMS && in_sizes[1] == NROWS * DIMS) {
        emb = (const float*)d_in[0];
        z   = (const float*)d_in[1];
    }
    float* out = (float*)d_out;

    vq_prep<<<(NCODES * 32 + 255) / 256, 256>>>(emb);

    cudaFuncSetAttribute(vq_main, cudaFuncAttributeMaxDynamicSharedMemorySize,
                         SMEM_BYTES);
    vq_main<<<NROWS / TM, 256, SMEM_BYTES>>>(z, emb, out);

    vq_finalize<<<1, 1>>>(out, out_size);
}